// round 11
// baseline (speedup 1.0000x reference)
#include <cuda_runtime.h>
#include <cuda_bf16.h>
#include <cstdint>

#define Bsz 8
#define Dm  4096
#define D3  12288
#define Ssz 16
#define FFm 16384

typedef unsigned long long u64;

// ---------------- scratch (allocation-free: __device__ globals) ----------------
__device__ float g_xn  [Bsz * Dm];
__device__ float g_z   [Bsz * D3];
__device__ float g_y   [Bsz * Dm];
__device__ float g_xout[Bsz * Dm];
__device__ float g_xn2 [Bsz * Dm];
__device__ float g_g1  [Bsz * FFm];
__device__ float g_g3  [Bsz * FFm];
__device__ float g_pole[Dm * Ssz];   // exp(log_poles), precomputed in k_rmsnorm_pre

// ---------------- packed f32x2 helpers ----------------
__device__ __forceinline__ u64 pack2(float lo, float hi) {
    u64 r;
    asm("mov.b64 %0, {%1, %2};" : "=l"(r) : "r"(__float_as_uint(lo)), "r"(__float_as_uint(hi)));
    return r;
}
__device__ __forceinline__ void unpack2(u64 v, float& lo, float& hi) {
    unsigned ulo, uhi;
    asm("mov.b64 {%0, %1}, %2;" : "=r"(ulo), "=r"(uhi) : "l"(v));
    lo = __uint_as_float(ulo); hi = __uint_as_float(uhi);
}

// ---------------- batched (B=8) split-K GEMV, 4-deep staging, 4 CTAs/SM ----------------
// W: [K, N] row-major. out[b,n] += sum_k xin[b,k]*W[k,n]
// 256 threads; thread owns 4 consecutive cols (LDG.128, streaming). Block covers
// 1024 cols. grid = (N/1024, K/KCHUNK[, z]).
// Staging depth 4 (16 live regs) keeps total ~60 regs -> 4 CTAs/SM = 32 warps/SM.
// x in smem duplicated (xb,xb), read as LDS.128.
// Epilogue: ONE red.global.add.v4.f32 per batch.
template<int KCHUNK, class XGen>
__device__ __forceinline__ void gemv4_body(const float* __restrict__ W,
                                           XGen xgen,
                                           float* __restrict__ out,
                                           int K, int N) {
    __shared__ __align__(16) u64 xs2[KCHUNK * 8];
    const int n0 = (blockIdx.x * 256 + threadIdx.x) * 4;
    const int k0 = blockIdx.y * KCHUNK;

    for (int t = threadIdx.x; t < KCHUNK * 8; t += 256) {
        int b = t / KCHUNK, k = t - b * KCHUNK;       // coalesced on k
        float v = xgen(b, k0 + k);
        xs2[k * 8 + b] = pack2(v, v);
    }
    __syncthreads();

    u64 acc01[8], acc23[8];
#pragma unroll
    for (int b = 0; b < 8; b++) { acc01[b] = pack2(0.f, 0.f); acc23[b] = pack2(0.f, 0.f); }

    const float4* Wp = reinterpret_cast<const float4*>(W + (size_t)k0 * N + n0);
    const size_t strd = (size_t)(N >> 2);

    for (int kb = 0; kb < KCHUNK; kb += 4) {
        // ---- load phase: 4 independent streaming LDG.128 in flight ----
        float4 w[4];
#pragma unroll
        for (int u = 0; u < 4; u++)
            w[u] = __ldcs(Wp + (size_t)(kb + u) * strd);

        // ---- compute phase ----
#pragma unroll
        for (int u = 0; u < 4; u++) {
            ulonglong2 wv = *reinterpret_cast<const ulonglong2*>(&w[u]);
            u64 w01 = wv.x, w23 = wv.y;
            const ulonglong2* xp = reinterpret_cast<const ulonglong2*>(xs2 + (kb + u) * 8);
#pragma unroll
            for (int j = 0; j < 4; j++) {
                ulonglong2 xb2 = xp[j];
                asm("fma.rn.f32x2 %0, %1, %2, %0;" : "+l"(acc01[2*j  ]) : "l"(w01), "l"(xb2.x));
                asm("fma.rn.f32x2 %0, %1, %2, %0;" : "+l"(acc23[2*j  ]) : "l"(w23), "l"(xb2.x));
                asm("fma.rn.f32x2 %0, %1, %2, %0;" : "+l"(acc01[2*j+1]) : "l"(w01), "l"(xb2.y));
                asm("fma.rn.f32x2 %0, %1, %2, %0;" : "+l"(acc23[2*j+1]) : "l"(w23), "l"(xb2.y));
            }
        }
    }

#pragma unroll
    for (int b = 0; b < 8; b++) {
        float a0, a1, a2, a3;
        unpack2(acc01[b], a0, a1);
        unpack2(acc23[b], a2, a3);
        float* ob = out + (size_t)b * N + n0;         // 16B-aligned
        asm volatile("red.global.add.v4.f32 [%0], {%1, %2, %3, %4};"
                     :: "l"(ob), "f"(a0), "f"(a1), "f"(a2), "f"(a3) : "memory");
    }
}

struct XPlain {
    const float* x; int K;
    __device__ __forceinline__ float operator()(int b, int k) const { return x[b * K + k]; }
};
struct XSilu {   // h = silu(g1) * g3, computed on the fly
    __device__ __forceinline__ float operator()(int b, int k) const {
        float a = g_g1[b * FFm + k];
        return (a / (1.f + __expf(-a))) * g_g3[b * FFm + k];
    }
};

__global__ void __launch_bounds__(256, 4) k_gemv_proj(const float* __restrict__ W) {
    gemv4_body<128>(W, XPlain{g_xn, Dm}, g_z, Dm, D3);
}
__global__ void __launch_bounds__(256, 4) k_gemv_out(const float* __restrict__ W) {
    gemv4_body<64>(W, XPlain{g_y, Dm}, g_xout, Dm, Dm);
}
__global__ void __launch_bounds__(256, 4) k_gemv_w13(const float* __restrict__ W1, const float* __restrict__ W3) {
    if (blockIdx.z == 0) gemv4_body<256>(W1, XPlain{g_xn2, Dm}, g_g1, Dm, FFm);
    else                 gemv4_body<256>(W3, XPlain{g_xn2, Dm}, g_g3, Dm, FFm);
}
__global__ void __launch_bounds__(256, 4) k_gemv_w2(const float* __restrict__ W, float* __restrict__ out_x) {
    gemv4_body<256>(W, XSilu{}, out_x, FFm, Dm);
}

// ---------------- rmsnorm ----------------
__device__ __forceinline__ void rmsnorm_body(const float* __restrict__ xr,
                                             const float* __restrict__ w,
                                             float* __restrict__ xo) {
    float ss = 0.f;
    for (int i = threadIdx.x; i < Dm; i += blockDim.x) { float v = xr[i]; ss += v * v; }
#pragma unroll
    for (int o = 16; o; o >>= 1) ss += __shfl_xor_sync(0xffffffffu, ss, o);
    __shared__ float red[32];
    int wid = threadIdx.x >> 5, lane = threadIdx.x & 31;
    if (lane == 0) red[wid] = ss;
    __syncthreads();
    int nw = blockDim.x >> 5;
    if (wid == 0) {
        float t = (lane < nw) ? red[lane] : 0.f;
#pragma unroll
        for (int o = 16; o; o >>= 1) t += __shfl_xor_sync(0xffffffffu, t, o);
        if (lane == 0) red[0] = t;
    }
    __syncthreads();
    float scale = rsqrtf(red[0] * (1.f / Dm) + 1e-6f);
    for (int i = threadIdx.x; i < Dm; i += blockDim.x) xo[i] = xr[i] * scale * w[i];
}

// pre-norm + zero g_z + precompute poles
__global__ void k_rmsnorm_pre(const float* __restrict__ x, const float* __restrict__ w,
                              const float* __restrict__ log_poles) {
    int b = blockIdx.x;
    for (int i = b * 1024 + threadIdx.x; i < Bsz * D3; i += Bsz * 1024) g_z[i] = 0.f;
    for (int i = b * 1024 + threadIdx.x; i < Dm * Ssz; i += Bsz * 1024)
        g_pole[i] = __expf(log_poles[i]);
    rmsnorm_body(x + b * Dm, w, g_xn + b * Dm);
}
// post-norm + zero g_g1/g_g3 + seed out_x with xout
__global__ void k_rmsnorm_post(const float* __restrict__ w, float* __restrict__ out_x) {
    int b = blockIdx.x;
    for (int i = b * 1024 + threadIdx.x; i < Bsz * FFm; i += Bsz * 1024) { g_g1[i] = 0.f; g_g3[i] = 0.f; }
    for (int i = threadIdx.x; i < Dm; i += 1024) out_x[b * Dm + i] = g_xout[b * Dm + i];
    rmsnorm_body(g_xout + b * Dm, w, g_xn2 + b * Dm);
}

// ---------------- fused FIR + IIR: one thread per (b, d) ----------------
__global__ void k_firiir(const float* __restrict__ fir_state,
                         const float* __restrict__ sf_weight,
                         const float* __restrict__ sf_bias,
                         const float* __restrict__ x,
                         const float* __restrict__ out_b,
                         const float* __restrict__ iir_state,
                         const float* __restrict__ D_res,
                         const float* __restrict__ residues,
                         float* __restrict__ out_fir,
                         float* __restrict__ out_iir) {
    int idx = blockIdx.x * blockDim.x + threadIdx.x;   // [0, 32768)
    int b = idx >> 12;
    int d = idx & (Dm - 1);
    int head = d >> 7;
    int i    = d & 127;
    int base = head * 384 + i;

    // ---- FIR taps (3 channels) ----
    float zp[3];
#pragma unroll
    for (int j = 0; j < 3; j++) {
        int n3 = base + j * 128;
        float u  = g_z[b * D3 + n3];
        float2 f = *reinterpret_cast<const float2*>(fir_state + (b * D3 + n3) * 2);
        const float* wr = sf_weight + n3 * 3;
        zp[j] = wr[2] * u + f.x * wr[0] + f.y * wr[1] + sf_bias[n3];
        *reinterpret_cast<float2*>(out_fir + (b * D3 + n3) * 2) = make_float2(f.y, u);
    }
    float x2  = zp[0];
    float x1v = zp[1] * zp[2];

    // ---- IIR over 16 states (float4, MLP=4) ----
    const float4* pp = reinterpret_cast<const float4*>(g_pole     + d * Ssz);
    const float4* rp = reinterpret_cast<const float4*>(residues   + d * Ssz);
    const float4* sp = reinterpret_cast<const float4*>(iir_state  + idx * Ssz);
    float4*       op = reinterpret_cast<float4*>      (out_iir    + idx * Ssz);

    float res = 0.f;
#pragma unroll
    for (int q = 0; q < 4; q++) {
        float4 pl = pp[q];
        float4 rr = rp[q];
        float4 st = sp[q];
        float4 ni;
        ni.x = pl.x * st.x + x1v;
        ni.y = pl.y * st.y + x1v;
        ni.z = pl.z * st.z + x1v;
        ni.w = pl.w * st.w + x1v;
        op[q] = ni;
        res += rr.x * ni.x + rr.y * ni.y + rr.z * ni.z + rr.w * ni.w;
    }

    g_y   [idx] = x2 * (res + D_res[d] * x1v);
    g_xout[idx] = x[idx] + out_b[d];
}

// ---------------- launcher ----------------
extern "C" void kernel_launch(void* const* d_in, const int* in_sizes, int n_in,
                              void* d_out, int out_size) {
    const float* x           = (const float*)d_in[0];
    const float* fir_state   = (const float*)d_in[1];
    const float* iir_state   = (const float*)d_in[2];
    const float* pre_norm_w  = (const float*)d_in[3];
    const float* proj_w      = (const float*)d_in[4];
    const float* sf_weight   = (const float*)d_in[5];
    const float* sf_bias     = (const float*)d_in[6];
    const float* D_res       = (const float*)d_in[7];
    const float* residues    = (const float*)d_in[8];
    const float* log_poles   = (const float*)d_in[9];
    const float* out_w       = (const float*)d_in[10];
    const float* out_b       = (const float*)d_in[11];
    const float* post_norm_w = (const float*)d_in[12];
    const float* mlp_w1      = (const float*)d_in[13];
    const float* mlp_w3      = (const float*)d_in[14];
    const float* mlp_w2      = (const float*)d_in[15];

    float* out_x   = (float*)d_out;                    // [8, 1, 4096]
    float* out_fir = out_x + Bsz * Dm;                 // [8, 12288, 2]
    float* out_iir = out_fir + Bsz * D3 * 2;           // [8, 4096, 16]

    k_rmsnorm_pre <<<Bsz, 1024>>>(x, pre_norm_w, log_poles);
    k_gemv_proj   <<<dim3(D3 / 1024, Dm / 128), 256>>>(proj_w);
    k_firiir      <<<(Bsz * Dm) / 256, 256>>>(fir_state, sf_weight, sf_bias, x, out_b,
                                              iir_state, D_res, residues, out_fir, out_iir);
    k_gemv_out    <<<dim3(Dm / 1024, Dm / 64), 256>>>(out_w);
    k_rmsnorm_post<<<Bsz, 1024>>>(post_norm_w, out_x);
    k_gemv_w13    <<<dim3(FFm / 1024, Dm / 256, 2), 256>>>(mlp_w1, mlp_w3);
    k_gemv_w2     <<<dim3(Dm / 1024, FFm / 256), 256>>>(mlp_w2, out_x);
}

// round 12
// speedup vs baseline: 1.0761x; 1.0761x over previous
#include <cuda_runtime.h>
#include <cuda_bf16.h>
#include <cstdint>

#define Bsz 8
#define Dm  4096
#define D3  12288
#define Ssz 16
#define FFm 16384

typedef unsigned long long u64;

// ---------------- scratch (allocation-free: __device__ globals) ----------------
__device__ float g_xn  [Bsz * Dm];
__device__ float g_z   [Bsz * D3];
__device__ float g_y   [Bsz * Dm];
__device__ float g_xout[Bsz * Dm];
__device__ float g_xn2 [Bsz * Dm];
__device__ float g_g1  [Bsz * FFm];
__device__ float g_g3  [Bsz * FFm];
__device__ float g_pole[Dm * Ssz];   // exp(log_poles), precomputed in k_rmsnorm_pre

// ---------------- packed f32x2 helpers ----------------
__device__ __forceinline__ u64 pack2(float lo, float hi) {
    u64 r;
    asm("mov.b64 %0, {%1, %2};" : "=l"(r) : "r"(__float_as_uint(lo)), "r"(__float_as_uint(hi)));
    return r;
}
__device__ __forceinline__ void unpack2(u64 v, float& lo, float& hi) {
    unsigned ulo, uhi;
    asm("mov.b64 {%0, %1}, %2;" : "=r"(ulo), "=r"(uhi) : "l"(v));
    lo = __uint_as_float(ulo); hi = __uint_as_float(uhi);
}

// ---------------- batched (B=8) split-K GEMV (R10 champion body) ----------------
// W: [K, N] row-major. out[b,n] += sum_k xin[b,k]*W[k,n]
// 256 threads; thread owns 4 consecutive cols (LDG.128, streaming). Block covers
// 1024 cols. grid = (N/1024, K/KCHUNK[, z]). Mainloop: stage 8 float4 loads into
// regs (MLP=8), then FMA phase. x in smem duplicated (xb,xb), read as LDS.128.
// Epilogue: ONE red.global.add.v4.f32 per batch.
template<int KCHUNK, class XGen>
__device__ __forceinline__ void gemv4_body(const float* __restrict__ W,
                                           XGen xgen,
                                           float* __restrict__ out,
                                           int K, int N) {
    __shared__ __align__(16) u64 xs2[KCHUNK * 8];
    const int n0 = (blockIdx.x * 256 + threadIdx.x) * 4;
    const int k0 = blockIdx.y * KCHUNK;

    for (int t = threadIdx.x; t < KCHUNK * 8; t += 256) {
        int b = t / KCHUNK, k = t - b * KCHUNK;       // coalesced on k
        float v = xgen(b, k0 + k);
        xs2[k * 8 + b] = pack2(v, v);
    }
    __syncthreads();

    u64 acc01[8], acc23[8];
#pragma unroll
    for (int b = 0; b < 8; b++) { acc01[b] = pack2(0.f, 0.f); acc23[b] = pack2(0.f, 0.f); }

    const float4* Wp = reinterpret_cast<const float4*>(W + (size_t)k0 * N + n0);
    const size_t strd = (size_t)(N >> 2);

    for (int kb = 0; kb < KCHUNK; kb += 8) {
        // ---- load phase: 8 independent streaming LDG.128 in flight ----
        float4 w[8];
#pragma unroll
        for (int u = 0; u < 8; u++)
            w[u] = __ldcs(Wp + (size_t)(kb + u) * strd);

        // ---- compute phase ----
#pragma unroll
        for (int u = 0; u < 8; u++) {
            ulonglong2 wv = *reinterpret_cast<const ulonglong2*>(&w[u]);
            u64 w01 = wv.x, w23 = wv.y;
            const ulonglong2* xp = reinterpret_cast<const ulonglong2*>(xs2 + (kb + u) * 8);
#pragma unroll
            for (int j = 0; j < 4; j++) {
                ulonglong2 xb2 = xp[j];
                asm("fma.rn.f32x2 %0, %1, %2, %0;" : "+l"(acc01[2*j  ]) : "l"(w01), "l"(xb2.x));
                asm("fma.rn.f32x2 %0, %1, %2, %0;" : "+l"(acc23[2*j  ]) : "l"(w23), "l"(xb2.x));
                asm("fma.rn.f32x2 %0, %1, %2, %0;" : "+l"(acc01[2*j+1]) : "l"(w01), "l"(xb2.y));
                asm("fma.rn.f32x2 %0, %1, %2, %0;" : "+l"(acc23[2*j+1]) : "l"(w23), "l"(xb2.y));
            }
        }
    }

#pragma unroll
    for (int b = 0; b < 8; b++) {
        float a0, a1, a2, a3;
        unpack2(acc01[b], a0, a1);                    // cols 0,1
        unpack2(acc23[b], a2, a3);                    // cols 2,3
        float* ob = out + (size_t)b * N + n0;         // 16B-aligned
        asm volatile("red.global.add.v4.f32 [%0], {%1, %2, %3, %4};"
                     :: "l"(ob), "f"(a0), "f"(a1), "f"(a2), "f"(a3) : "memory");
    }
}

struct XPlain {
    const float* x; int K;
    __device__ __forceinline__ float operator()(int b, int k) const { return x[b * K + k]; }
};
struct XSilu {   // h = silu(g1) * g3, computed on the fly
    __device__ __forceinline__ float operator()(int b, int k) const {
        float a = g_g1[b * FFm + k];
        return (a / (1.f + __expf(-a))) * g_g3[b * FFm + k];
    }
};

__global__ void __launch_bounds__(256, 2) k_gemv_proj(const float* __restrict__ W) {
    gemv4_body<128>(W, XPlain{g_xn, Dm}, g_z, Dm, D3);
}
__global__ void __launch_bounds__(256, 2) k_gemv_out(const float* __restrict__ W) {
    gemv4_body<32>(W, XPlain{g_y, Dm}, g_xout, Dm, Dm);
}
__global__ void __launch_bounds__(256, 2) k_gemv_w13(const float* __restrict__ W1, const float* __restrict__ W3) {
    if (blockIdx.z == 0) gemv4_body<256>(W1, XPlain{g_xn2, Dm}, g_g1, Dm, FFm);
    else                 gemv4_body<256>(W3, XPlain{g_xn2, Dm}, g_g3, Dm, FFm);
}
__global__ void __launch_bounds__(256, 2) k_gemv_w2(const float* __restrict__ W, float* __restrict__ out_x) {
    gemv4_body<256>(W, XSilu{}, out_x, FFm, Dm);
}

// ---------------- rmsnorm ----------------
__device__ __forceinline__ void rmsnorm_body(const float* __restrict__ xr,
                                             const float* __restrict__ w,
                                             float* __restrict__ xo) {
    float ss = 0.f;
    for (int i = threadIdx.x; i < Dm; i += blockDim.x) { float v = xr[i]; ss += v * v; }
#pragma unroll
    for (int o = 16; o; o >>= 1) ss += __shfl_xor_sync(0xffffffffu, ss, o);
    __shared__ float red[32];
    int wid = threadIdx.x >> 5, lane = threadIdx.x & 31;
    if (lane == 0) red[wid] = ss;
    __syncthreads();
    int nw = blockDim.x >> 5;
    if (wid == 0) {
        float t = (lane < nw) ? red[lane] : 0.f;
#pragma unroll
        for (int o = 16; o; o >>= 1) t += __shfl_xor_sync(0xffffffffu, t, o);
        if (lane == 0) red[0] = t;
    }
    __syncthreads();
    float scale = rsqrtf(red[0] * (1.f / Dm) + 1e-6f);
    for (int i = threadIdx.x; i < Dm; i += blockDim.x) xo[i] = xr[i] * scale * w[i];
}

// pre-norm + zero g_z + precompute poles
__global__ void k_rmsnorm_pre(const float* __restrict__ x, const float* __restrict__ w,
                              const float* __restrict__ log_poles) {
    int b = blockIdx.x;
    for (int i = b * 1024 + threadIdx.x; i < Bsz * D3; i += Bsz * 1024) g_z[i] = 0.f;
    for (int i = b * 1024 + threadIdx.x; i < Dm * Ssz; i += Bsz * 1024)
        g_pole[i] = __expf(log_poles[i]);
    rmsnorm_body(x + b * Dm, w, g_xn + b * Dm);
}
// post-norm + zero g_g1/g_g3 + seed out_x with xout
__global__ void k_rmsnorm_post(const float* __restrict__ w, float* __restrict__ out_x) {
    int b = blockIdx.x;
    for (int i = b * 1024 + threadIdx.x; i < Bsz * FFm; i += Bsz * 1024) { g_g1[i] = 0.f; g_g3[i] = 0.f; }
    for (int i = threadIdx.x; i < Dm; i += 1024) out_x[b * Dm + i] = g_xout[b * Dm + i];
    rmsnorm_body(g_xout + b * Dm, w, g_xn2 + b * Dm);
}

// ---------------- fused FIR + IIR: one thread per (b, d) ----------------
__global__ void k_firiir(const float* __restrict__ fir_state,
                         const float* __restrict__ sf_weight,
                         const float* __restrict__ sf_bias,
                         const float* __restrict__ x,
                         const float* __restrict__ out_b,
                         const float* __restrict__ iir_state,
                         const float* __restrict__ D_res,
                         const float* __restrict__ residues,
                         float* __restrict__ out_fir,
                         float* __restrict__ out_iir) {
    int idx = blockIdx.x * blockDim.x + threadIdx.x;   // [0, 32768)
    int b = idx >> 12;
    int d = idx & (Dm - 1);
    int head = d >> 7;
    int i    = d & 127;
    int base = head * 384 + i;

    // ---- FIR taps (3 channels) ----
    float zp[3];
#pragma unroll
    for (int j = 0; j < 3; j++) {
        int n3 = base + j * 128;
        float u  = g_z[b * D3 + n3];
        float2 f = *reinterpret_cast<const float2*>(fir_state + (b * D3 + n3) * 2);
        const float* wr = sf_weight + n3 * 3;
        zp[j] = wr[2] * u + f.x * wr[0] + f.y * wr[1] + sf_bias[n3];
        *reinterpret_cast<float2*>(out_fir + (b * D3 + n3) * 2) = make_float2(f.y, u);
    }
    float x2  = zp[0];
    float x1v = zp[1] * zp[2];

    // ---- IIR over 16 states (float4, MLP=4) ----
    const float4* pp = reinterpret_cast<const float4*>(g_pole     + d * Ssz);
    const float4* rp = reinterpret_cast<const float4*>(residues   + d * Ssz);
    const float4* sp = reinterpret_cast<const float4*>(iir_state  + idx * Ssz);
    float4*       op = reinterpret_cast<float4*>      (out_iir    + idx * Ssz);

    float res = 0.f;
#pragma unroll
    for (int q = 0; q < 4; q++) {
        float4 pl = pp[q];
        float4 rr = rp[q];
        float4 st = sp[q];
        float4 ni;
        ni.x = pl.x * st.x + x1v;
        ni.y = pl.y * st.y + x1v;
        ni.z = pl.z * st.z + x1v;
        ni.w = pl.w * st.w + x1v;
        op[q] = ni;
        res += rr.x * ni.x + rr.y * ni.y + rr.z * ni.z + rr.w * ni.w;
    }

    g_y   [idx] = x2 * (res + D_res[d] * x1v);
    g_xout[idx] = x[idx] + out_b[d];
}

// ---------------- launcher ----------------
extern "C" void kernel_launch(void* const* d_in, const int* in_sizes, int n_in,
                              void* d_out, int out_size) {
    const float* x           = (const float*)d_in[0];
    const float* fir_state   = (const float*)d_in[1];
    const float* iir_state   = (const float*)d_in[2];
    const float* pre_norm_w  = (const float*)d_in[3];
    const float* proj_w      = (const float*)d_in[4];
    const float* sf_weight   = (const float*)d_in[5];
    const float* sf_bias     = (const float*)d_in[6];
    const float* D_res       = (const float*)d_in[7];
    const float* residues    = (const float*)d_in[8];
    const float* log_poles   = (const float*)d_in[9];
    const float* out_w       = (const float*)d_in[10];
    const float* out_b       = (const float*)d_in[11];
    const float* post_norm_w = (const float*)d_in[12];
    const float* mlp_w1      = (const float*)d_in[13];
    const float* mlp_w3      = (const float*)d_in[14];
    const float* mlp_w2      = (const float*)d_in[15];

    float* out_x   = (float*)d_out;                    // [8, 1, 4096]
    float* out_fir = out_x + Bsz * Dm;                 // [8, 12288, 2]
    float* out_iir = out_fir + Bsz * D3 * 2;           // [8, 4096, 16]

    k_rmsnorm_pre <<<Bsz, 1024>>>(x, pre_norm_w, log_poles);
    k_gemv_proj   <<<dim3(D3 / 1024, Dm / 128), 256>>>(proj_w);
    k_firiir      <<<(Bsz * Dm) / 256, 256>>>(fir_state, sf_weight, sf_bias, x, out_b,
                                              iir_state, D_res, residues, out_fir, out_iir);
    k_gemv_out    <<<dim3(Dm / 1024, Dm / 32), 256>>>(out_w);
    k_rmsnorm_post<<<Bsz, 1024>>>(post_norm_w, out_x);
    k_gemv_w13    <<<dim3(FFm / 1024, Dm / 256, 2), 256>>>(mlp_w1, mlp_w3);
    k_gemv_w2     <<<dim3(Dm / 1024, FFm / 256), 256>>>(mlp_w2, out_x);
}

// round 13
// speedup vs baseline: 1.1116x; 1.0330x over previous
#include <cuda_runtime.h>
#include <cuda_bf16.h>
#include <cstdint>

#define Bsz 8
#define Dm  4096
#define D3  12288
#define Ssz 16
#define FFm 16384

typedef unsigned long long u64;

// ---------------- scratch (allocation-free: __device__ globals) ----------------
__device__ float g_xn  [Bsz * Dm];
__device__ float g_z   [Bsz * D3];
__device__ float g_x2  [Bsz * Dm];
__device__ float g_x1v [Bsz * Dm];
__device__ float g_y   [Bsz * Dm];
__device__ float g_xout[Bsz * Dm];
__device__ float g_xn2 [Bsz * Dm];
__device__ float g_g1  [Bsz * FFm];
__device__ float g_g3  [Bsz * FFm];
__device__ float g_pole[Dm * Ssz];   // exp(log_poles), precomputed in k_fir

// ---------------- packed f32x2 helpers ----------------
__device__ __forceinline__ u64 pack2(float lo, float hi) {
    u64 r;
    asm("mov.b64 %0, {%1, %2};" : "=l"(r) : "r"(__float_as_uint(lo)), "r"(__float_as_uint(hi)));
    return r;
}
__device__ __forceinline__ void unpack2(u64 v, float& lo, float& hi) {
    unsigned ulo, uhi;
    asm("mov.b64 {%0, %1}, %2;" : "=r"(ulo), "=r"(uhi) : "l"(v));
    lo = __uint_as_float(ulo); hi = __uint_as_float(uhi);
}

// ---------------- batched (B=8) split-K GEMV (R10 champion body) ----------------
// W: [K, N] row-major. out[b,n] += sum_k xin[b,k]*W[k,n]
// 256 threads; thread owns 4 consecutive cols (LDG.128, streaming). Block covers
// 1024 cols. grid = (N/1024, K/KCHUNK[, z]). Mainloop: stage 8 float4 loads into
// regs (MLP=8), then FMA phase. x in smem duplicated (xb,xb), read as LDS.128.
// Epilogue: ONE red.global.add.v4.f32 per batch.
template<int KCHUNK, class XGen>
__device__ __forceinline__ void gemv4_body(const float* __restrict__ W,
                                           XGen xgen,
                                           float* __restrict__ out,
                                           int K, int N) {
    __shared__ __align__(16) u64 xs2[KCHUNK * 8];
    const int n0 = (blockIdx.x * 256 + threadIdx.x) * 4;
    const int k0 = blockIdx.y * KCHUNK;

    for (int t = threadIdx.x; t < KCHUNK * 8; t += 256) {
        int b = t / KCHUNK, k = t - b * KCHUNK;       // coalesced on k
        float v = xgen(b, k0 + k);
        xs2[k * 8 + b] = pack2(v, v);
    }
    __syncthreads();

    u64 acc01[8], acc23[8];
#pragma unroll
    for (int b = 0; b < 8; b++) { acc01[b] = pack2(0.f, 0.f); acc23[b] = pack2(0.f, 0.f); }

    const float4* Wp = reinterpret_cast<const float4*>(W + (size_t)k0 * N + n0);
    const size_t strd = (size_t)(N >> 2);

    for (int kb = 0; kb < KCHUNK; kb += 8) {
        // ---- load phase: 8 independent streaming LDG.128 in flight ----
        float4 w[8];
#pragma unroll
        for (int u = 0; u < 8; u++)
            w[u] = __ldcs(Wp + (size_t)(kb + u) * strd);

        // ---- compute phase ----
#pragma unroll
        for (int u = 0; u < 8; u++) {
            ulonglong2 wv = *reinterpret_cast<const ulonglong2*>(&w[u]);
            u64 w01 = wv.x, w23 = wv.y;
            const ulonglong2* xp = reinterpret_cast<const ulonglong2*>(xs2 + (kb + u) * 8);
#pragma unroll
            for (int j = 0; j < 4; j++) {
                ulonglong2 xb2 = xp[j];
                asm("fma.rn.f32x2 %0, %1, %2, %0;" : "+l"(acc01[2*j  ]) : "l"(w01), "l"(xb2.x));
                asm("fma.rn.f32x2 %0, %1, %2, %0;" : "+l"(acc23[2*j  ]) : "l"(w23), "l"(xb2.x));
                asm("fma.rn.f32x2 %0, %1, %2, %0;" : "+l"(acc01[2*j+1]) : "l"(w01), "l"(xb2.y));
                asm("fma.rn.f32x2 %0, %1, %2, %0;" : "+l"(acc23[2*j+1]) : "l"(w23), "l"(xb2.y));
            }
        }
    }

#pragma unroll
    for (int b = 0; b < 8; b++) {
        float a0, a1, a2, a3;
        unpack2(acc01[b], a0, a1);                    // cols 0,1
        unpack2(acc23[b], a2, a3);                    // cols 2,3
        float* ob = out + (size_t)b * N + n0;         // 16B-aligned
        asm volatile("red.global.add.v4.f32 [%0], {%1, %2, %3, %4};"
                     :: "l"(ob), "f"(a0), "f"(a1), "f"(a2), "f"(a3) : "memory");
    }
}

struct XPlain {
    const float* x; int K;
    __device__ __forceinline__ float operator()(int b, int k) const { return x[b * K + k]; }
};
struct XSilu {   // h = silu(g1) * g3, computed on the fly
    __device__ __forceinline__ float operator()(int b, int k) const {
        float a = g_g1[b * FFm + k];
        return (a / (1.f + __expf(-a))) * g_g3[b * FFm + k];
    }
};

__global__ void __launch_bounds__(256, 2) k_gemv_proj(const float* __restrict__ W) {
    gemv4_body<128>(W, XPlain{g_xn, Dm}, g_z, Dm, D3);
}
__global__ void __launch_bounds__(256, 2) k_gemv_out(const float* __restrict__ W) {
    gemv4_body<32>(W, XPlain{g_y, Dm}, g_xout, Dm, Dm);
}
__global__ void __launch_bounds__(256, 2) k_gemv_w13(const float* __restrict__ W1, const float* __restrict__ W3) {
    if (blockIdx.z == 0) gemv4_body<256>(W1, XPlain{g_xn2, Dm}, g_g1, Dm, FFm);
    else                 gemv4_body<256>(W3, XPlain{g_xn2, Dm}, g_g3, Dm, FFm);
}
__global__ void __launch_bounds__(256, 2) k_gemv_w2(const float* __restrict__ W, float* __restrict__ out_x) {
    gemv4_body<256>(W, XSilu{}, out_x, FFm, Dm);
}

// ---------------- rmsnorm ----------------
__device__ __forceinline__ void rmsnorm_body(const float* __restrict__ xr,
                                             const float* __restrict__ w,
                                             float* __restrict__ xo) {
    float ss = 0.f;
    for (int i = threadIdx.x; i < Dm; i += blockDim.x) { float v = xr[i]; ss += v * v; }
#pragma unroll
    for (int o = 16; o; o >>= 1) ss += __shfl_xor_sync(0xffffffffu, ss, o);
    __shared__ float red[32];
    int wid = threadIdx.x >> 5, lane = threadIdx.x & 31;
    if (lane == 0) red[wid] = ss;
    __syncthreads();
    int nw = blockDim.x >> 5;
    if (wid == 0) {
        float t = (lane < nw) ? red[lane] : 0.f;
#pragma unroll
        for (int o = 16; o; o >>= 1) t += __shfl_xor_sync(0xffffffffu, t, o);
        if (lane == 0) red[0] = t;
    }
    __syncthreads();
    float scale = rsqrtf(red[0] * (1.f / Dm) + 1e-6f);
    for (int i = threadIdx.x; i < Dm; i += blockDim.x) xo[i] = xr[i] * scale * w[i];
}

// 64 blocks: blocks 0-7 do rmsnorm(b); ALL blocks share the zeroing of g_z.
__global__ void k_rmsnorm_pre(const float* __restrict__ x, const float* __restrict__ w) {
    for (int i = blockIdx.x * 1024 + threadIdx.x; i < Bsz * D3; i += 64 * 1024) g_z[i] = 0.f;
    if (blockIdx.x < Bsz) {
        int b = blockIdx.x;
        rmsnorm_body(x + b * Dm, w, g_xn + b * Dm);
    }
}
// 64 blocks: blocks 0-7 do rmsnorm(b); ALL blocks zero g_g1/g_g3 + seed out_x.
__global__ void k_rmsnorm_post(const float* __restrict__ w, float* __restrict__ out_x) {
    for (int i = blockIdx.x * 1024 + threadIdx.x; i < Bsz * FFm; i += 64 * 1024) {
        g_g1[i] = 0.f; g_g3[i] = 0.f;
    }
    for (int i = blockIdx.x * 1024 + threadIdx.x; i < Bsz * Dm; i += 64 * 1024)
        out_x[i] = g_xout[i];
    if (blockIdx.x < Bsz) {
        int b = blockIdx.x;
        rmsnorm_body(g_xout + b * Dm, w, g_xn2 + b * Dm);
    }
}

// ---------------- FIR taps + seed g_xout + precompute poles ----------------
__global__ void k_fir(const float* __restrict__ fir_state,
                      const float* __restrict__ sf_weight,
                      const float* __restrict__ sf_bias,
                      const float* __restrict__ x,
                      const float* __restrict__ out_b,
                      const float* __restrict__ log_poles,
                      float* __restrict__ out_fir) {
    int idx = blockIdx.x * blockDim.x + threadIdx.x;   // [0, 32768)
    int b = idx >> 12;
    int d = idx & (Dm - 1);
    int head = d >> 7;
    int i    = d & 127;
    int base = head * 384 + i;

    {
        int p0 = idx * 2;
        g_pole[p0]     = __expf(log_poles[p0]);
        g_pole[p0 + 1] = __expf(log_poles[p0 + 1]);
    }

    float zp[3];
#pragma unroll
    for (int j = 0; j < 3; j++) {
        int n3 = base + j * 128;
        float u  = g_z[b * D3 + n3];
        float2 f = *reinterpret_cast<const float2*>(fir_state + (b * D3 + n3) * 2);
        const float* wr = sf_weight + n3 * 3;
        zp[j] = wr[2] * u + f.x * wr[0] + f.y * wr[1] + sf_bias[n3];
        *reinterpret_cast<float2*>(out_fir + (b * D3 + n3) * 2) = make_float2(f.y, u);
    }
    g_x2 [b * Dm + d] = zp[0];
    g_x1v[b * Dm + d] = zp[1] * zp[2];
    g_xout[b * Dm + d] = x[b * Dm + d] + out_b[d];
}

// ---------------- IIR: one thread per (b, d, s-pair) ----------------
__global__ void k_iir(const float* __restrict__ iir_state,
                      const float* __restrict__ D_res,
                      const float* __restrict__ residues,
                      float* __restrict__ out_iir) {
    int idx = blockIdx.x * blockDim.x + threadIdx.x;   // [0, 262144)
    int sg = idx & 7;            // s-pair: covers s = 2*sg, 2*sg+1
    int bd = idx >> 3;           // b*Dm + d
    int d  = bd & (Dm - 1);
    int ds = d * Ssz + sg * 2;

    float2 pole = *reinterpret_cast<const float2*>(g_pole + ds);
    float2 r    = *reinterpret_cast<const float2*>(residues + ds);
    float2 st   = *reinterpret_cast<const float2*>(iir_state + bd * Ssz + sg * 2);
    float x1v   = g_x1v[bd];

    float n0 = pole.x * st.x + x1v;
    float n1 = pole.y * st.y + x1v;
    *reinterpret_cast<float2*>(out_iir + bd * Ssz + sg * 2) = make_float2(n0, n1);

    float c = r.x * n0 + r.y * n1;
#pragma unroll
    for (int o = 1; o < 8; o <<= 1) c += __shfl_xor_sync(0xffffffffu, c, o);
    if (sg == 0)
        g_y[bd] = g_x2[bd] * (c + D_res[d] * x1v);
}

// ---------------- launcher ----------------
extern "C" void kernel_launch(void* const* d_in, const int* in_sizes, int n_in,
                              void* d_out, int out_size) {
    const float* x           = (const float*)d_in[0];
    const float* fir_state   = (const float*)d_in[1];
    const float* iir_state   = (const float*)d_in[2];
    const float* pre_norm_w  = (const float*)d_in[3];
    const float* proj_w      = (const float*)d_in[4];
    const float* sf_weight   = (const float*)d_in[5];
    const float* sf_bias     = (const float*)d_in[6];
    const float* D_res       = (const float*)d_in[7];
    const float* residues    = (const float*)d_in[8];
    const float* log_poles   = (const float*)d_in[9];
    const float* out_w       = (const float*)d_in[10];
    const float* out_b       = (const float*)d_in[11];
    const float* post_norm_w = (const float*)d_in[12];
    const float* mlp_w1      = (const float*)d_in[13];
    const float* mlp_w3      = (const float*)d_in[14];
    const float* mlp_w2      = (const float*)d_in[15];

    float* out_x   = (float*)d_out;                    // [8, 1, 4096]
    float* out_fir = out_x + Bsz * Dm;                 // [8, 12288, 2]
    float* out_iir = out_fir + Bsz * D3 * 2;           // [8, 4096, 16]

    k_rmsnorm_pre <<<64, 1024>>>(x, pre_norm_w);
    k_gemv_proj   <<<dim3(D3 / 1024, Dm / 128), 256>>>(proj_w);
    k_fir         <<<(Bsz * Dm) / 256, 256>>>(fir_state, sf_weight, sf_bias, x, out_b, log_poles, out_fir);
    k_iir         <<<(Bsz * Dm * 8) / 256, 256>>>(iir_state, D_res, residues, out_iir);
    k_gemv_out    <<<dim3(Dm / 1024, Dm / 32), 256>>>(out_w);
    k_rmsnorm_post<<<64, 1024>>>(post_norm_w, out_x);
    k_gemv_w13    <<<dim3(FFm / 1024, Dm / 256, 2), 256>>>(mlp_w1, mlp_w3);
    k_gemv_w2     <<<dim3(Dm / 1024, FFm / 256), 256>>>(mlp_w2, out_x);
}

// round 14
// speedup vs baseline: 1.1348x; 1.0208x over previous
#include <cuda_runtime.h>
#include <cuda_bf16.h>
#include <cstdint>

#define Bsz 8
#define Dm  4096
#define D3  12288
#define Ssz 16
#define FFm 16384

typedef unsigned long long u64;

// ---------------- scratch (allocation-free: __device__ globals) ----------------
__device__ float g_xn  [Bsz * Dm];
__device__ float g_z   [Bsz * D3];
__device__ float g_x2  [Bsz * Dm];
__device__ float g_x1v [Bsz * Dm];
__device__ float g_y   [Bsz * Dm];
__device__ float g_xout[Bsz * Dm];
__device__ float g_xn2 [Bsz * Dm];
__device__ float g_g1  [Bsz * FFm];
__device__ float g_g3  [Bsz * FFm];
__device__ float g_pole[Dm * Ssz];   // exp(log_poles), precomputed in k_fir

// ---------------- packed f32x2 helpers ----------------
__device__ __forceinline__ u64 pack2(float lo, float hi) {
    u64 r;
    asm("mov.b64 %0, {%1, %2};" : "=l"(r) : "r"(__float_as_uint(lo)), "r"(__float_as_uint(hi)));
    return r;
}
__device__ __forceinline__ void unpack2(u64 v, float& lo, float& hi) {
    unsigned ulo, uhi;
    asm("mov.b64 {%0, %1}, %2;" : "=r"(ulo), "=r"(uhi) : "l"(v));
    lo = __uint_as_float(ulo); hi = __uint_as_float(uhi);
}

// ---------------- batched (B=8) split-K GEMV (champion body) ----------------
// W: [K, N] row-major. out[b,n] += sum_k xin[b,k]*W[k,n]
// 256 threads; thread owns 4 consecutive cols (LDG.128, streaming). Block covers
// 1024 cols. grid = (N/1024, K/KCHUNK[, z]). Mainloop: stage 8 float4 loads into
// regs (MLP=8), then FMA phase. x in smem duplicated (xb,xb), read as LDS.128.
// Epilogue: ONE red.global.add.v4.f32 per batch.
// KCHUNK chosen per-GEMV for wave-slot utilization at 296 block slots.
template<int KCHUNK, class XGen>
__device__ __forceinline__ void gemv4_body(const float* __restrict__ W,
                                           XGen xgen,
                                           float* __restrict__ out,
                                           int K, int N) {
    __shared__ __align__(16) u64 xs2[KCHUNK * 8];
    const int n0 = (blockIdx.x * 256 + threadIdx.x) * 4;
    const int k0 = blockIdx.y * KCHUNK;

    for (int t = threadIdx.x; t < KCHUNK * 8; t += 256) {
        int b = t / KCHUNK, k = t - b * KCHUNK;       // coalesced on k
        float v = xgen(b, k0 + k);
        xs2[k * 8 + b] = pack2(v, v);
    }
    __syncthreads();

    u64 acc01[8], acc23[8];
#pragma unroll
    for (int b = 0; b < 8; b++) { acc01[b] = pack2(0.f, 0.f); acc23[b] = pack2(0.f, 0.f); }

    const float4* Wp = reinterpret_cast<const float4*>(W + (size_t)k0 * N + n0);
    const size_t strd = (size_t)(N >> 2);

    for (int kb = 0; kb < KCHUNK; kb += 8) {
        // ---- load phase: 8 independent streaming LDG.128 in flight ----
        float4 w[8];
#pragma unroll
        for (int u = 0; u < 8; u++)
            w[u] = __ldcs(Wp + (size_t)(kb + u) * strd);

        // ---- compute phase ----
#pragma unroll
        for (int u = 0; u < 8; u++) {
            ulonglong2 wv = *reinterpret_cast<const ulonglong2*>(&w[u]);
            u64 w01 = wv.x, w23 = wv.y;
            const ulonglong2* xp = reinterpret_cast<const ulonglong2*>(xs2 + (kb + u) * 8);
#pragma unroll
            for (int j = 0; j < 4; j++) {
                ulonglong2 xb2 = xp[j];
                asm("fma.rn.f32x2 %0, %1, %2, %0;" : "+l"(acc01[2*j  ]) : "l"(w01), "l"(xb2.x));
                asm("fma.rn.f32x2 %0, %1, %2, %0;" : "+l"(acc23[2*j  ]) : "l"(w23), "l"(xb2.x));
                asm("fma.rn.f32x2 %0, %1, %2, %0;" : "+l"(acc01[2*j+1]) : "l"(w01), "l"(xb2.y));
                asm("fma.rn.f32x2 %0, %1, %2, %0;" : "+l"(acc23[2*j+1]) : "l"(w23), "l"(xb2.y));
            }
        }
    }

#pragma unroll
    for (int b = 0; b < 8; b++) {
        float a0, a1, a2, a3;
        unpack2(acc01[b], a0, a1);                    // cols 0,1
        unpack2(acc23[b], a2, a3);                    // cols 2,3
        float* ob = out + (size_t)b * N + n0;         // 16B-aligned
        asm volatile("red.global.add.v4.f32 [%0], {%1, %2, %3, %4};"
                     :: "l"(ob), "f"(a0), "f"(a1), "f"(a2), "f"(a3) : "memory");
    }
}

struct XPlain {
    const float* x; int K;
    __device__ __forceinline__ float operator()(int b, int k) const { return x[b * K + k]; }
};
struct XSilu {   // h = silu(g1) * g3, computed on the fly
    __device__ __forceinline__ float operator()(int b, int k) const {
        float a = g_g1[b * FFm + k];
        return (a / (1.f + __expf(-a))) * g_g3[b * FFm + k];
    }
};

__global__ void __launch_bounds__(256, 2) k_gemv_proj(const float* __restrict__ W) {
    gemv4_body<64>(W, XPlain{g_xn, Dm}, g_z, Dm, D3);
}
__global__ void __launch_bounds__(256, 2) k_gemv_out(const float* __restrict__ W) {
    gemv4_body<32>(W, XPlain{g_y, Dm}, g_xout, Dm, Dm);
}
__global__ void __launch_bounds__(256, 2) k_gemv_w13(const float* __restrict__ W1, const float* __restrict__ W3) {
    if (blockIdx.z == 0) gemv4_body<256>(W1, XPlain{g_xn2, Dm}, g_g1, Dm, FFm);
    else                 gemv4_body<256>(W3, XPlain{g_xn2, Dm}, g_g3, Dm, FFm);
}
__global__ void __launch_bounds__(256, 2) k_gemv_w2(const float* __restrict__ W, float* __restrict__ out_x) {
    gemv4_body<128>(W, XSilu{}, out_x, FFm, Dm);
}

// ---------------- rmsnorm ----------------
__device__ __forceinline__ void rmsnorm_body(const float* __restrict__ xr,
                                             const float* __restrict__ w,
                                             float* __restrict__ xo) {
    float ss = 0.f;
    for (int i = threadIdx.x; i < Dm; i += blockDim.x) { float v = xr[i]; ss += v * v; }
#pragma unroll
    for (int o = 16; o; o >>= 1) ss += __shfl_xor_sync(0xffffffffu, ss, o);
    __shared__ float red[32];
    int wid = threadIdx.x >> 5, lane = threadIdx.x & 31;
    if (lane == 0) red[wid] = ss;
    __syncthreads();
    int nw = blockDim.x >> 5;
    if (wid == 0) {
        float t = (lane < nw) ? red[lane] : 0.f;
#pragma unroll
        for (int o = 16; o; o >>= 1) t += __shfl_xor_sync(0xffffffffu, t, o);
        if (lane == 0) red[0] = t;
    }
    __syncthreads();
    float scale = rsqrtf(red[0] * (1.f / Dm) + 1e-6f);
    for (int i = threadIdx.x; i < Dm; i += blockDim.x) xo[i] = xr[i] * scale * w[i];
}

// 64 blocks: blocks 0-7 do rmsnorm(b); ALL blocks share the zeroing of g_z.
__global__ void k_rmsnorm_pre(const float* __restrict__ x, const float* __restrict__ w) {
    for (int i = blockIdx.x * 1024 + threadIdx.x; i < Bsz * D3; i += 64 * 1024) g_z[i] = 0.f;
    if (blockIdx.x < Bsz) {
        int b = blockIdx.x;
        rmsnorm_body(x + b * Dm, w, g_xn + b * Dm);
    }
}
// 64 blocks: blocks 0-7 do rmsnorm(b); ALL blocks zero g_g1/g_g3 + seed out_x.
__global__ void k_rmsnorm_post(const float* __restrict__ w, float* __restrict__ out_x) {
    for (int i = blockIdx.x * 1024 + threadIdx.x; i < Bsz * FFm; i += 64 * 1024) {
        g_g1[i] = 0.f; g_g3[i] = 0.f;
    }
    for (int i = blockIdx.x * 1024 + threadIdx.x; i < Bsz * Dm; i += 64 * 1024)
        out_x[i] = g_xout[i];
    if (blockIdx.x < Bsz) {
        int b = blockIdx.x;
        rmsnorm_body(g_xout + b * Dm, w, g_xn2 + b * Dm);
    }
}

// ---------------- FIR taps + seed g_xout + precompute poles ----------------
__global__ void k_fir(const float* __restrict__ fir_state,
                      const float* __restrict__ sf_weight,
                      const float* __restrict__ sf_bias,
                      const float* __restrict__ x,
                      const float* __restrict__ out_b,
                      const float* __restrict__ log_poles,
                      float* __restrict__ out_fir) {
    int idx = blockIdx.x * blockDim.x + threadIdx.x;   // [0, 32768)
    int b = idx >> 12;
    int d = idx & (Dm - 1);
    int head = d >> 7;
    int i    = d & 127;
    int base = head * 384 + i;

    {
        int p0 = idx * 2;
        g_pole[p0]     = __expf(log_poles[p0]);
        g_pole[p0 + 1] = __expf(log_poles[p0 + 1]);
    }

    float zp[3];
#pragma unroll
    for (int j = 0; j < 3; j++) {
        int n3 = base + j * 128;
        float u  = g_z[b * D3 + n3];
        float2 f = *reinterpret_cast<const float2*>(fir_state + (b * D3 + n3) * 2);
        const float* wr = sf_weight + n3 * 3;
        zp[j] = wr[2] * u + f.x * wr[0] + f.y * wr[1] + sf_bias[n3];
        *reinterpret_cast<float2*>(out_fir + (b * D3 + n3) * 2) = make_float2(f.y, u);
    }
    g_x2 [b * Dm + d] = zp[0];
    g_x1v[b * Dm + d] = zp[1] * zp[2];
    g_xout[b * Dm + d] = x[b * Dm + d] + out_b[d];
}

// ---------------- IIR: one thread per (b, d, s-pair) ----------------
__global__ void k_iir(const float* __restrict__ iir_state,
                      const float* __restrict__ D_res,
                      const float* __restrict__ residues,
                      float* __restrict__ out_iir) {
    int idx = blockIdx.x * blockDim.x + threadIdx.x;   // [0, 262144)
    int sg = idx & 7;            // s-pair: covers s = 2*sg, 2*sg+1
    int bd = idx >> 3;           // b*Dm + d
    int d  = bd & (Dm - 1);
    int ds = d * Ssz + sg * 2;

    float2 pole = *reinterpret_cast<const float2*>(g_pole + ds);
    float2 r    = *reinterpret_cast<const float2*>(residues + ds);
    float2 st   = *reinterpret_cast<const float2*>(iir_state + bd * Ssz + sg * 2);
    float x1v   = g_x1v[bd];

    float n0 = pole.x * st.x + x1v;
    float n1 = pole.y * st.y + x1v;
    *reinterpret_cast<float2*>(out_iir + bd * Ssz + sg * 2) = make_float2(n0, n1);

    float c = r.x * n0 + r.y * n1;
#pragma unroll
    for (int o = 1; o < 8; o <<= 1) c += __shfl_xor_sync(0xffffffffu, c, o);
    if (sg == 0)
        g_y[bd] = g_x2[bd] * (c + D_res[d] * x1v);
}

// ---------------- launcher ----------------
extern "C" void kernel_launch(void* const* d_in, const int* in_sizes, int n_in,
                              void* d_out, int out_size) {
    const float* x           = (const float*)d_in[0];
    const float* fir_state   = (const float*)d_in[1];
    const float* iir_state   = (const float*)d_in[2];
    const float* pre_norm_w  = (const float*)d_in[3];
    const float* proj_w      = (const float*)d_in[4];
    const float* sf_weight   = (const float*)d_in[5];
    const float* sf_bias     = (const float*)d_in[6];
    const float* D_res       = (const float*)d_in[7];
    const float* residues    = (const float*)d_in[8];
    const float* log_poles   = (const float*)d_in[9];
    const float* out_w       = (const float*)d_in[10];
    const float* out_b       = (const float*)d_in[11];
    const float* post_norm_w = (const float*)d_in[12];
    const float* mlp_w1      = (const float*)d_in[13];
    const float* mlp_w3      = (const float*)d_in[14];
    const float* mlp_w2      = (const float*)d_in[15];

    float* out_x   = (float*)d_out;                    // [8, 1, 4096]
    float* out_fir = out_x + Bsz * Dm;                 // [8, 12288, 2]
    float* out_iir = out_fir + Bsz * D3 * 2;           // [8, 4096, 16]

    k_rmsnorm_pre <<<64, 1024>>>(x, pre_norm_w);
    k_gemv_proj   <<<dim3(D3 / 1024, Dm / 64), 256>>>(proj_w);
    k_fir         <<<(Bsz * Dm) / 256, 256>>>(fir_state, sf_weight, sf_bias, x, out_b, log_poles, out_fir);
    k_iir         <<<(Bsz * Dm * 8) / 256, 256>>>(iir_state, D_res, residues, out_iir);
    k_gemv_out    <<<dim3(Dm / 1024, Dm / 32), 256>>>(out_w);
    k_rmsnorm_post<<<64, 1024>>>(post_norm_w, out_x);
    k_gemv_w13    <<<dim3(FFm / 1024, Dm / 256, 2), 256>>>(mlp_w1, mlp_w3);
    k_gemv_w2     <<<dim3(Dm / 1024, FFm / 128), 256>>>(mlp_w2, out_x);
}